// round 13
// baseline (speedup 1.0000x reference)
#include <cuda_runtime.h>
#include <cuda_bf16.h>

#define FLAT 524288          // 128 * 64 * 64

// ---------------- device scratch (no allocation) ----------------
__device__ float g_partA[512 * 1024];                 // [blk][sq(32)][b(32)]
__device__ float g_ev[4 * 32 * 8];                    // [s][b][q]
__device__ float g_G2[(size_t)128 * 4096 * 36];       // [o][ij][k]  ~75.5 MB

// ---------------- packed f32x2 helpers ----------------
typedef unsigned long long ull;
__device__ __forceinline__ ull pack2(float a, float b) {
    ull r; asm("mov.b64 %0, {%1,%2};" : "=l"(r) : "f"(a), "f"(b)); return r;
}
__device__ __forceinline__ void unpack2(ull v, float& a, float& b) {
    asm("mov.b64 {%0,%1}, %2;" : "=f"(a), "=f"(b) : "l"(v));
}
__device__ __forceinline__ ull ffma2(ull a, ull b, ull c) {
    ull d; asm("fma.rn.f32x2 %0, %1, %2, %3;" : "=l"(d) : "l"(a), "l"(b), "l"(c));
    return d;
}

// =========================================================================
// kA: stage-A partial reductions, register double-buffered (frozen from R10;
// this round it sits in the PROFILED 4th launch slot).
// grid 512 = (c:128) x (igroup:4), 256 threads.
// =========================================================================
__global__ __launch_bounds__(256) void kA(const float* __restrict__ x,
                                          const float* __restrict__ Win) {
    int bx = blockIdx.x;
    int c = bx >> 2;
    int i0 = (bx & 3) << 4;
    int t = threadIdx.x, w = t >> 5, l = t & 31;

    __shared__ float subS[4][64][33];   // [s][j][b]
    __shared__ float Ws[64][36];        // [j][sq]

    float acc0 = 0.f, acc1 = 0.f, acc2 = 0.f, acc3 = 0.f;
    int s_w = w >> 1;

    float wreg[8];
    float4 xr[8];   // 4 passes x 2 rows

    {
        const float* wp = Win + (size_t)c * 4096 + (size_t)i0 * 64;
#pragma unroll
        for (int u = 0; u < 8; ++u) {
            int idx = t + 256 * u;
            int sq = idx >> 6, j = idx & 63;
            wreg[u] = wp[(size_t)sq * FLAT + j];
        }
#pragma unroll
        for (int pass = 0; pass < 4; ++pass) {
            int b = w + pass * 8;
            const float* xp = x + ((((size_t)b * 128 + c) * 128) + 2 * i0) * 128;
            xr[2 * pass]     = *(const float4*)(xp + 4 * l);
            xr[2 * pass + 1] = *(const float4*)(xp + 128 + 4 * l);
        }
    }

    for (int ii = 0; ii < 16; ++ii) {
#pragma unroll
        for (int u = 0; u < 8; ++u) {
            int idx = t + 256 * u;
            int sq = idx >> 6, j = idx & 63;
            Ws[j][sq] = wreg[u];
        }
#pragma unroll
        for (int pass = 0; pass < 4; ++pass) {
            int b = w + pass * 8;
            float4 r0 = xr[2 * pass], r1 = xr[2 * pass + 1];
            int j0 = 2 * l;
            float a = r0.x, bb = r0.y, cc = r1.x, dd = r1.y;
            subS[0][j0][b] = 0.5f * (a + bb + cc + dd);
            subS[1][j0][b] = 0.5f * (a + bb - cc - dd);
            subS[2][j0][b] = 0.5f * (a - bb + cc - dd);
            subS[3][j0][b] = 0.5f * (a - bb - cc + dd);
            a = r0.z; bb = r0.w; cc = r1.z; dd = r1.w;
            subS[0][j0 + 1][b] = 0.5f * (a + bb + cc + dd);
            subS[1][j0 + 1][b] = 0.5f * (a + bb - cc - dd);
            subS[2][j0 + 1][b] = 0.5f * (a - bb + cc - dd);
            subS[3][j0 + 1][b] = 0.5f * (a - bb - cc + dd);
        }
        __syncthreads();

        if (ii < 15) {
            int i = i0 + ii + 1;
            const float* wp = Win + (size_t)c * 4096 + (size_t)i * 64;
#pragma unroll
            for (int u = 0; u < 8; ++u) {
                int idx = t + 256 * u;
                int sq = idx >> 6, j = idx & 63;
                wreg[u] = wp[(size_t)sq * FLAT + j];
            }
#pragma unroll
            for (int pass = 0; pass < 4; ++pass) {
                int b = w + pass * 8;
                const float* xp = x + ((((size_t)b * 128 + c) * 128) + 2 * i) * 128;
                xr[2 * pass]     = *(const float4*)(xp + 4 * l);
                xr[2 * pass + 1] = *(const float4*)(xp + 128 + 4 * l);
            }
        }

#pragma unroll 8
        for (int j = 0; j < 64; ++j) {
            float4 wv = *(const float4*)&Ws[j][w * 4];
            float sv = subS[s_w][j][l];
            acc0 = fmaf(sv, wv.x, acc0);
            acc1 = fmaf(sv, wv.y, acc1);
            acc2 = fmaf(sv, wv.z, acc2);
            acc3 = fmaf(sv, wv.w, acc3);
        }
        __syncthreads();
    }
    float* op = g_partA + (size_t)bx * 1024 + (w * 4) * 32 + l;
    op[0] = acc0; op[32] = acc1; op[64] = acc2; op[96] = acc3;
}

// =========================================================================
// kG with zbase param (same math as R10 merged kernel; launched 3x with
// gridDim (256,4,1) so kA can occupy the profiled 4th launch slot).
// =========================================================================
__global__ __launch_bounds__(256) void kG(const float* __restrict__ fuseW,
                                          const float* __restrict__ Wout,
                                          const float* __restrict__ bout,
                                          int zb) {
    __shared__ float As[32][68];
    __shared__ float Bs[32][128];
    int s = blockIdx.y;
    int t = threadIdx.x;
    int ij0 = blockIdx.x * 16;

    if (zb < 2) {
        int o0 = zb * 64;
        int to = t & 31, tn = t >> 5;

        ull acc[8][2];
#pragma unroll
        for (int a = 0; a < 8; ++a) { acc[a][0] = 0ull; acc[a][1] = 0ull; }

        const float* wbase = Wout + (size_t)s * FLAT * 8 + (size_t)ij0 * 8;

        for (int c0 = 0; c0 < 128; c0 += 32) {
            for (int idx = t; idx < 2048; idx += 256) {
                int o = idx >> 5, cc = idx & 31;
                As[cc][o] = fuseW[(o0 + o) * 128 + c0 + cc];
            }
            for (int idx = t; idx < 4096; idx += 256) {
                int cc = idx >> 7, r = idx & 127;
                Bs[cc][r] = wbase[(size_t)(c0 + cc) * 32768 + r];
            }
            __syncthreads();
#pragma unroll 4
            for (int cc = 0; cc < 32; ++cc) {
                ulonglong2 bv = *(const ulonglong2*)&Bs[cc][4 * to];
                float4 av0 = *(const float4*)&As[cc][tn * 8];
                float4 av1 = *(const float4*)&As[cc][tn * 8 + 4];
                ull aa[8];
                aa[0] = pack2(av0.x, av0.x); aa[1] = pack2(av0.y, av0.y);
                aa[2] = pack2(av0.z, av0.z); aa[3] = pack2(av0.w, av0.w);
                aa[4] = pack2(av1.x, av1.x); aa[5] = pack2(av1.y, av1.y);
                aa[6] = pack2(av1.z, av1.z); aa[7] = pack2(av1.w, av1.w);
#pragma unroll
                for (int oo = 0; oo < 8; ++oo) {
                    acc[oo][0] = ffma2(aa[oo], bv.x, acc[oo][0]);
                    acc[oo][1] = ffma2(aa[oo], bv.y, acc[oo][1]);
                }
            }
            __syncthreads();
        }

        int ij = ij0 + (to >> 1);
        int q = (to & 1) * 4;
#pragma unroll
        for (int oo = 0; oo < 8; ++oo) {
            int o = o0 + tn * 8 + oo;
            float v0, v1, v2, v3;
            unpack2(acc[oo][0], v0, v1);
            unpack2(acc[oo][1], v2, v3);
            *(float4*)&g_G2[((size_t)o * 4096 + ij) * 36 + s * 8 + q] =
                make_float4(0.5f * v0, 0.5f * v1, 0.5f * v2, 0.5f * v3);
        }
    } else {
        int ij = t & 15, og = t >> 4;
        float acc[8];
#pragma unroll
        for (int a = 0; a < 8; ++a) acc[a] = 0.f;

        const float* bbase = bout + (size_t)s * FLAT + ij0;

        for (int c0 = 0; c0 < 128; c0 += 32) {
            for (int idx = t; idx < 4096; idx += 256) {
                int o = idx >> 5, cc = idx & 31;
                Bs[cc][o] = fuseW[o * 128 + c0 + cc];
            }
            for (int idx = t; idx < 512; idx += 256) {
                int cc = idx >> 4, ij2 = idx & 15;
                As[cc][ij2] = bbase[(size_t)(c0 + cc) * 4096 + ij2];
            }
            __syncthreads();
#pragma unroll 4
            for (int cc = 0; cc < 32; ++cc) {
                float bs = As[cc][ij];
                const float* ap = &Bs[cc][og * 8];
#pragma unroll
                for (int oo = 0; oo < 8; ++oo)
                    acc[oo] = fmaf(ap[oo], bs, acc[oo]);
            }
            __syncthreads();
        }
#pragma unroll
        for (int oo = 0; oo < 8; ++oo) {
            int o = og * 8 + oo;
            g_G2[((size_t)o * 4096 + ij0 + ij) * 36 + 32 + s] = 0.5f * acc[oo];
        }
    }
}

// =========================================================================
// kB: one warp per (s,b), grid (4,32), 32 threads (frozen).
// =========================================================================
__device__ __forceinline__ float2 cmul(float2 a, float2 b) {
    return make_float2(a.x * b.x - a.y * b.y, a.x * b.y + a.y * b.x);
}
__device__ __forceinline__ float2 cadd(float2 a, float2 b) {
    return make_float2(a.x + b.x, a.y + b.y);
}

__global__ __launch_bounds__(32) void kB(const float* __restrict__ qinb,
                                         const float* __restrict__ qw) {
    int s = blockIdx.x;
    int b = blockIdx.y;
    int l = threadIdx.x;

    __shared__ float2 sp[256];

    int q = l & 7, pg = l >> 3;
    float sum = 0.f;
    const float* pp = g_partA + (s * 8 + q) * 32 + b;
#pragma unroll 16
    for (int blk = pg; blk < 512; blk += 4) sum += pp[(size_t)blk * 1024];
    sum += __shfl_xor_sync(0xffffffffu, sum, 8);
    sum += __shfl_xor_sync(0xffffffffu, sum, 16);
    float qv = sum + qinb[s * 8 + q];

    for (int tt = 0; tt < 8; ++tt) {
        int p = l + 32 * tt;
        sp[p] = make_float2(p == 0 ? 1.f : 0.f, 0.f);
    }
    __syncwarp();

    for (int qq = 0; qq < 8; ++qq) {
        float ang = 0.5f * __shfl_sync(0xffffffffu, qv, qq);
        float cg = cosf(ang), sg = sinf(ang);
        int pos = 7 - qq, S = 1 << pos;
#pragma unroll
        for (int tt = 0; tt < 4; ++tt) {
            int p = l + 32 * tt;
            int lo = ((p >> pos) << (pos + 1)) | (p & (S - 1));
            int hi = lo | S;
            float2 v0 = sp[lo], v1 = sp[hi];
            sp[lo] = make_float2(cg * v0.x + sg * v1.y, cg * v0.y - sg * v1.x);
            sp[hi] = make_float2(sg * v0.y + cg * v1.x, -sg * v0.x + cg * v1.y);
        }
        __syncwarp();
    }

    for (int lay = 0; lay < 3; ++lay) {
        for (int qq = 0; qq < 8; ++qq) {
            const float* wp = qw + (((size_t)s * 3 + lay) * 8 + qq) * 3;
            float phi = wp[0], th = wp[1], om = wp[2];
            float ct = cosf(0.5f * th), snt = sinf(0.5f * th);
            float ap = -0.5f * (phi + om), am = -0.5f * (phi - om);
            float2 ep = make_float2(cosf(ap), sinf(ap));
            float2 em = make_float2(cosf(am), sinf(am));
            float2 U00 = make_float2(ep.x * ct, ep.y * ct);
            float2 U01 = make_float2(-em.x * snt, em.y * snt);
            float2 U10 = make_float2(em.x * snt, em.y * snt);
            float2 U11 = make_float2(ep.x * ct, -ep.y * ct);
            int pos = 7 - qq, S = 1 << pos;
#pragma unroll
            for (int tt = 0; tt < 4; ++tt) {
                int p = l + 32 * tt;
                int lo = ((p >> pos) << (pos + 1)) | (p & (S - 1));
                int hi = lo | S;
                float2 v0 = sp[lo], v1 = sp[hi];
                sp[lo] = cadd(cmul(U00, v0), cmul(U01, v1));
                sp[hi] = cadd(cmul(U10, v0), cmul(U11, v1));
            }
            __syncwarp();
        }
        for (int e = 0; e < 8; ++e) {
            int ctrl = (e < 7) ? e : 7;
            int tgt = (e < 7) ? e + 1 : 0;
            int pc = 7 - ctrl, pt = 7 - tgt;
            int plo = pc < pt ? pc : pt;
            int phi_ = pc < pt ? pt : pc;
            int Sc = 1 << pc, St = 1 << pt;
#pragma unroll
            for (int tt = 0; tt < 2; ++tt) {
                int r = l + 32 * tt;
                int tmp = ((r >> plo) << (plo + 1)) | (r & ((1 << plo) - 1));
                int p = ((tmp >> phi_) << (phi_ + 1)) | (tmp & ((1 << phi_) - 1));
                p |= Sc;
                float2 a_ = sp[p], b_ = sp[p | St];
                sp[p] = b_; sp[p | St] = a_;
            }
            __syncwarp();
        }
    }

    float evq[8] = {0, 0, 0, 0, 0, 0, 0, 0};
    for (int tt = 0; tt < 8; ++tt) {
        int p = l + 32 * tt;
        float2 v = sp[p];
        float pr = v.x * v.x + v.y * v.y;
#pragma unroll
        for (int qq = 0; qq < 8; ++qq)
            evq[qq] += ((p >> (7 - qq)) & 1) ? -pr : pr;
    }
#pragma unroll
    for (int qq = 0; qq < 8; ++qq)
        for (int off = 16; off; off >>= 1)
            evq[qq] += __shfl_xor_sync(0xffffffffu, evq[qq], off);
    if (l < 8) g_ev[((size_t)s * 32 + b) * 8 + l] = evq[l];
}

// =========================================================================
// kApply v3: iteration-ahead x prefetch + no G2 register hoist (frees regs
// -> higher occupancy) + conflict-free stride-36 G2 smem rows.
// grid (ijt:32, o:128), 256 threads.
// =========================================================================
__device__ __forceinline__ float4 apply_ps(const float* __restrict__ gr,
                                           const float* __restrict__ er) {
    float4 g8 = *(const float4*)&gr[32];
    float ps0 = g8.x, ps1 = g8.y, ps2 = g8.z, ps3 = g8.w;
    float4 e, g;
    e = *(const float4*)&er[0];  g = *(const float4*)&gr[0];
    ps0 = fmaf(e.x, g.x, ps0); ps0 = fmaf(e.y, g.y, ps0);
    ps0 = fmaf(e.z, g.z, ps0); ps0 = fmaf(e.w, g.w, ps0);
    e = *(const float4*)&er[4];  g = *(const float4*)&gr[4];
    ps0 = fmaf(e.x, g.x, ps0); ps0 = fmaf(e.y, g.y, ps0);
    ps0 = fmaf(e.z, g.z, ps0); ps0 = fmaf(e.w, g.w, ps0);
    e = *(const float4*)&er[8];  g = *(const float4*)&gr[8];
    ps1 = fmaf(e.x, g.x, ps1); ps1 = fmaf(e.y, g.y, ps1);
    ps1 = fmaf(e.z, g.z, ps1); ps1 = fmaf(e.w, g.w, ps1);
    e = *(const float4*)&er[12]; g = *(const float4*)&gr[12];
    ps1 = fmaf(e.x, g.x, ps1); ps1 = fmaf(e.y, g.y, ps1);
    ps1 = fmaf(e.z, g.z, ps1); ps1 = fmaf(e.w, g.w, ps1);
    e = *(const float4*)&er[16]; g = *(const float4*)&gr[16];
    ps2 = fmaf(e.x, g.x, ps2); ps2 = fmaf(e.y, g.y, ps2);
    ps2 = fmaf(e.z, g.z, ps2); ps2 = fmaf(e.w, g.w, ps2);
    e = *(const float4*)&er[20]; g = *(const float4*)&gr[20];
    ps2 = fmaf(e.x, g.x, ps2); ps2 = fmaf(e.y, g.y, ps2);
    ps2 = fmaf(e.z, g.z, ps2); ps2 = fmaf(e.w, g.w, ps2);
    e = *(const float4*)&er[24]; g = *(const float4*)&gr[24];
    ps3 = fmaf(e.x, g.x, ps3); ps3 = fmaf(e.y, g.y, ps3);
    ps3 = fmaf(e.z, g.z, ps3); ps3 = fmaf(e.w, g.w, ps3);
    e = *(const float4*)&er[28]; g = *(const float4*)&gr[28];
    ps3 = fmaf(e.x, g.x, ps3); ps3 = fmaf(e.y, g.y, ps3);
    ps3 = fmaf(e.z, g.z, ps3); ps3 = fmaf(e.w, g.w, ps3);
    return make_float4(ps0, ps1, ps2, ps3);
}

__global__ __launch_bounds__(256) void kApply(const float* __restrict__ x,
                                              const float* __restrict__ fuseb,
                                              float* __restrict__ out) {
    int ijt = blockIdx.x;   // 0..31
    int o = blockIdx.y;     // 0..127
    int ij0 = ijt * 128;
    int t = threadIdx.x;

    __shared__ float G2s[128][36];   // stride 36: 16B-aligned + conflict-free
    __shared__ float evs[32][36];

    const float* gsrc = g_G2 + ((size_t)o * 4096 + ij0) * 36;
    for (int idx = t; idx < 4608; idx += 256) {
        G2s[0][idx] = gsrc[idx];     // contiguous copy (same 36-stride layout)
    }
    for (int idx = t; idx < 1024; idx += 256) {
        int b = idx >> 5, k = idx & 31;
        evs[b][k] = g_ev[((size_t)(k >> 3) * 32 + b) * 8 + (k & 7)];
    }
    __syncthreads();

    int bi = t >> 7, ijl = t & 127;
    int i_ = ijt * 2 + (ijl >> 6), j_ = ijl & 63;
    float fb = fuseb[o];
    const float* gr = &G2s[ijl][0];

    size_t rowoff = ((size_t)o * 128 + 2 * i_) * 128 + 2 * j_;

    // prefetch bo = 0 (batches bi*2, bi*2+1)
    size_t pbase = (size_t)(bi * 2) * 2097152 + rowoff;
    float2 xa0 = *(const float2*)(x + pbase);
    float2 xa1 = *(const float2*)(x + pbase + 128);
    float2 xb0 = *(const float2*)(x + pbase + 2097152);
    float2 xb1 = *(const float2*)(x + pbase + 2097152 + 128);

    for (int bo = 0; bo < 8; ++bo) {
        int b0 = bo * 4 + bi * 2;
        size_t cbase = (size_t)b0 * 2097152 + rowoff;

        // prefetch next iteration's 4 x-loads (overlap with compute+stores)
        float2 na0, na1, nb0, nb1;
        if (bo < 7) {
            size_t nb = cbase + (size_t)4 * 2097152;
            na0 = *(const float2*)(x + nb);
            na1 = *(const float2*)(x + nb + 128);
            nb0 = *(const float2*)(x + nb + 2097152);
            nb1 = *(const float2*)(x + nb + 2097152 + 128);
        }

        {   // batch b0
            float4 ps = apply_ps(gr, &evs[b0][0]);
            float t00 = ps.x + ps.y + ps.z + ps.w;
            float t01 = ps.x + ps.y - ps.z - ps.w;
            float t10 = ps.x - ps.y + ps.z - ps.w;
            float t11 = ps.x - ps.y - ps.z + ps.w;
            *(float2*)(out + cbase)       = make_float2(xa0.x + fb + t00, xa0.y + fb + t01);
            *(float2*)(out + cbase + 128) = make_float2(xa1.x + fb + t10, xa1.y + fb + t11);
        }
        {   // batch b0+1
            float4 ps = apply_ps(gr, &evs[b0 + 1][0]);
            float t00 = ps.x + ps.y + ps.z + ps.w;
            float t01 = ps.x + ps.y - ps.z - ps.w;
            float t10 = ps.x - ps.y + ps.z - ps.w;
            float t11 = ps.x - ps.y - ps.z + ps.w;
            *(float2*)(out + cbase + 2097152)       = make_float2(xb0.x + fb + t00, xb0.y + fb + t01);
            *(float2*)(out + cbase + 2097152 + 128) = make_float2(xb1.x + fb + t10, xb1.y + fb + t11);
        }
        xa0 = na0; xa1 = na1; xb0 = nb0; xb1 = nb1;
    }
}

// =========================================================================
// 6 launches; kA is the 4th (profiled this round).
// Deps: kB needs kA; kApply needs kG(all z) + kB.
// =========================================================================
extern "C" void kernel_launch(void* const* d_in, const int* in_sizes, int n_in,
                              void* d_out, int out_size) {
    const float* x     = (const float*)d_in[0];
    const float* qinW  = (const float*)d_in[1];
    const float* qinb  = (const float*)d_in[2];
    const float* qw    = (const float*)d_in[3];
    const float* qoutW = (const float*)d_in[4];
    const float* qoutb = (const float*)d_in[5];
    const float* fuseW = (const float*)d_in[6];
    const float* fuseb = (const float*)d_in[7];
    float* out = (float*)d_out;

    kG<<<dim3(256, 4), 256>>>(fuseW, qoutW, qoutb, 0);
    kG<<<dim3(256, 4), 256>>>(fuseW, qoutW, qoutb, 1);
    kG<<<dim3(256, 4), 256>>>(fuseW, qoutW, qoutb, 2);
    kA<<<512, 256>>>(x, qinW);
    kB<<<dim3(4, 32), 32>>>(qinb, qw);
    kApply<<<dim3(32, 128), 256>>>(x, fuseb, out);
}

// round 15
// speedup vs baseline: 1.0926x; 1.0926x over previous
#include <cuda_runtime.h>
#include <cuda_bf16.h>

#define FLAT 524288          // 128 * 64 * 64

// ---------------- device scratch (no allocation) ----------------
__device__ float g_partA[512 * 1024];                 // [blk][sq(32)][b(32)]
__device__ float g_ev[4 * 32 * 8];                    // [s][b][q]
__device__ float g_G2[(size_t)128 * 4096 * 36];       // [o][ij][k]  ~75.5 MB

// ---------------- packed f32x2 helpers ----------------
typedef unsigned long long ull;
__device__ __forceinline__ ull pack2(float a, float b) {
    ull r; asm("mov.b64 %0, {%1,%2};" : "=l"(r) : "f"(a), "f"(b)); return r;
}
__device__ __forceinline__ void unpack2(ull v, float& a, float& b) {
    asm("mov.b64 {%0,%1}, %2;" : "=f"(a), "=f"(b) : "l"(v));
}
__device__ __forceinline__ ull ffma2(ull a, ull b, ull c) {
    ull d; asm("fma.rn.f32x2 %0, %1, %2, %3;" : "=l"(d) : "l"(a), "l"(b), "l"(c));
    return d;
}

// =========================================================================
// kA: stage-A partial reductions, register double-buffered (frozen; 100.2us).
// grid 512 = (c:128) x (igroup:4), 256 threads.
// =========================================================================
__global__ __launch_bounds__(256) void kA(const float* __restrict__ x,
                                          const float* __restrict__ Win) {
    int bx = blockIdx.x;
    int c = bx >> 2;
    int i0 = (bx & 3) << 4;
    int t = threadIdx.x, w = t >> 5, l = t & 31;

    __shared__ float subS[4][64][33];   // [s][j][b]
    __shared__ float Ws[64][36];        // [j][sq]

    float acc0 = 0.f, acc1 = 0.f, acc2 = 0.f, acc3 = 0.f;
    int s_w = w >> 1;

    float wreg[8];
    float4 xr[8];

    {
        const float* wp = Win + (size_t)c * 4096 + (size_t)i0 * 64;
#pragma unroll
        for (int u = 0; u < 8; ++u) {
            int idx = t + 256 * u;
            int sq = idx >> 6, j = idx & 63;
            wreg[u] = wp[(size_t)sq * FLAT + j];
        }
#pragma unroll
        for (int pass = 0; pass < 4; ++pass) {
            int b = w + pass * 8;
            const float* xp = x + ((((size_t)b * 128 + c) * 128) + 2 * i0) * 128;
            xr[2 * pass]     = *(const float4*)(xp + 4 * l);
            xr[2 * pass + 1] = *(const float4*)(xp + 128 + 4 * l);
        }
    }

    for (int ii = 0; ii < 16; ++ii) {
#pragma unroll
        for (int u = 0; u < 8; ++u) {
            int idx = t + 256 * u;
            int sq = idx >> 6, j = idx & 63;
            Ws[j][sq] = wreg[u];
        }
#pragma unroll
        for (int pass = 0; pass < 4; ++pass) {
            int b = w + pass * 8;
            float4 r0 = xr[2 * pass], r1 = xr[2 * pass + 1];
            int j0 = 2 * l;
            float a = r0.x, bb = r0.y, cc = r1.x, dd = r1.y;
            subS[0][j0][b] = 0.5f * (a + bb + cc + dd);
            subS[1][j0][b] = 0.5f * (a + bb - cc - dd);
            subS[2][j0][b] = 0.5f * (a - bb + cc - dd);
            subS[3][j0][b] = 0.5f * (a - bb - cc + dd);
            a = r0.z; bb = r0.w; cc = r1.z; dd = r1.w;
            subS[0][j0 + 1][b] = 0.5f * (a + bb + cc + dd);
            subS[1][j0 + 1][b] = 0.5f * (a + bb - cc - dd);
            subS[2][j0 + 1][b] = 0.5f * (a - bb + cc - dd);
            subS[3][j0 + 1][b] = 0.5f * (a - bb - cc + dd);
        }
        __syncthreads();

        if (ii < 15) {
            int i = i0 + ii + 1;
            const float* wp = Win + (size_t)c * 4096 + (size_t)i * 64;
#pragma unroll
            for (int u = 0; u < 8; ++u) {
                int idx = t + 256 * u;
                int sq = idx >> 6, j = idx & 63;
                wreg[u] = wp[(size_t)sq * FLAT + j];
            }
#pragma unroll
            for (int pass = 0; pass < 4; ++pass) {
                int b = w + pass * 8;
                const float* xp = x + ((((size_t)b * 128 + c) * 128) + 2 * i) * 128;
                xr[2 * pass]     = *(const float4*)(xp + 4 * l);
                xr[2 * pass + 1] = *(const float4*)(xp + 128 + 4 * l);
            }
        }

#pragma unroll 8
        for (int j = 0; j < 64; ++j) {
            float4 wv = *(const float4*)&Ws[j][w * 4];
            float sv = subS[s_w][j][l];
            acc0 = fmaf(sv, wv.x, acc0);
            acc1 = fmaf(sv, wv.y, acc1);
            acc2 = fmaf(sv, wv.z, acc2);
            acc3 = fmaf(sv, wv.w, acc3);
        }
        __syncthreads();
    }
    float* op = g_partA + (size_t)bx * 1024 + (w * 4) * 32 + l;
    op[0] = acc0; op[32] = acc1; op[64] = acc2; op[96] = acc3;
}

// =========================================================================
// kGw: WEIGHTS part, restructured fma-bound tile.
// grid (ijg:256, s:4), 256 threads. Block: 128 o x (16 ij x 8 q = 128 n).
// Thread: 4 o x 16 n. Per cc: 32 FFMA2 (64 fma-cyc) vs 8 MOV + 5 LDS.
// B reads are warp-uniform (broadcast LDS); A reads conflict-free float4.
// =========================================================================
__global__ __launch_bounds__(256) void kGw(const float* __restrict__ fuseW,
                                           const float* __restrict__ Wout) {
    __shared__ float As[32][132];   // [cc][o:128]
    __shared__ float Bs[32][128];   // [cc][n:128]
    int ij0 = blockIdx.x * 16;
    int s = blockIdx.y;
    int t = threadIdx.x;
    int to = t & 31;                // o-group: o = 4*to .. 4*to+3
    int tn = t >> 5;                // n-group: n = 16*tn .. 16*tn+15 (warp-uniform)

    ull acc[4][8];
#pragma unroll
    for (int a = 0; a < 4; ++a)
#pragma unroll
        for (int m = 0; m < 8; ++m) acc[a][m] = 0ull;

    const float* wbase = Wout + (size_t)s * FLAT * 8 + (size_t)ij0 * 8;

    for (int c0 = 0; c0 < 128; c0 += 32) {
        for (int idx = t; idx < 4096; idx += 256) {
            int o = idx >> 5, cc = idx & 31;
            As[cc][o] = fuseW[o * 128 + c0 + cc];
        }
        for (int idx = t; idx < 4096; idx += 256) {
            int cc = idx >> 7, r = idx & 127;
            Bs[cc][r] = wbase[(size_t)(c0 + cc) * 32768 + r];
        }
        __syncthreads();
#pragma unroll 4
        for (int cc = 0; cc < 32; ++cc) {
            float4 av = *(const float4*)&As[cc][4 * to];
            ull aa0 = pack2(av.x, av.x);
            ull aa1 = pack2(av.y, av.y);
            ull aa2 = pack2(av.z, av.z);
            ull aa3 = pack2(av.w, av.w);
            const ulonglong2* bp = (const ulonglong2*)&Bs[cc][16 * tn];
            ulonglong2 b01 = bp[0];
            ulonglong2 b23 = bp[1];
            ulonglong2 b45 = bp[2];
            ulonglong2 b67 = bp[3];
            ull bv[8] = {b01.x, b01.y, b23.x, b23.y, b45.x, b45.y, b67.x, b67.y};
#pragma unroll
            for (int m = 0; m < 8; ++m) {
                acc[0][m] = ffma2(aa0, bv[m], acc[0][m]);
                acc[1][m] = ffma2(aa1, bv[m], acc[1][m]);
                acc[2][m] = ffma2(aa2, bv[m], acc[2][m]);
                acc[3][m] = ffma2(aa3, bv[m], acc[3][m]);
            }
        }
        __syncthreads();
    }

    // epilogue: thread covers o = 4*to+oo, ij = ij0+2*tn+{0,1}, q = 0..7
#pragma unroll
    for (int oo = 0; oo < 4; ++oo) {
        int o = 4 * to + oo;
        float v[16];
#pragma unroll
        for (int m = 0; m < 8; ++m) unpack2(acc[oo][m], v[2 * m], v[2 * m + 1]);
#pragma unroll
        for (int jj = 0; jj < 2; ++jj) {
            int ij = ij0 + 2 * tn + jj;
            float* dst = &g_G2[((size_t)o * 4096 + ij) * 36 + s * 8];
            *(float4*)dst = make_float4(0.5f * v[8 * jj],     0.5f * v[8 * jj + 1],
                                        0.5f * v[8 * jj + 2], 0.5f * v[8 * jj + 3]);
            *(float4*)(dst + 4) = make_float4(0.5f * v[8 * jj + 4], 0.5f * v[8 * jj + 5],
                                              0.5f * v[8 * jj + 6], 0.5f * v[8 * jj + 7]);
        }
    }
}

// =========================================================================
// kGb: BIAS slots (frozen logic). grid (256, 4), 256 threads.
// =========================================================================
__global__ __launch_bounds__(256) void kGb(const float* __restrict__ fuseW,
                                           const float* __restrict__ bout) {
    __shared__ float As[32][16];
    __shared__ float Bs[32][132];
    int ij0 = blockIdx.x * 16;
    int s = blockIdx.y;
    int t = threadIdx.x;
    int ij = t & 15, og = t >> 4;
    float acc[8];
#pragma unroll
    for (int a = 0; a < 8; ++a) acc[a] = 0.f;

    const float* bbase = bout + (size_t)s * FLAT + ij0;

    for (int c0 = 0; c0 < 128; c0 += 32) {
        for (int idx = t; idx < 4096; idx += 256) {
            int o = idx >> 5, cc = idx & 31;
            Bs[cc][o] = fuseW[o * 128 + c0 + cc];
        }
        for (int idx = t; idx < 512; idx += 256) {
            int cc = idx >> 4, ij2 = idx & 15;
            As[cc][ij2] = bbase[(size_t)(c0 + cc) * 4096 + ij2];
        }
        __syncthreads();
#pragma unroll 4
        for (int cc = 0; cc < 32; ++cc) {
            float bs = As[cc][ij];
            const float* ap = &Bs[cc][og * 8];
#pragma unroll
            for (int oo = 0; oo < 8; ++oo)
                acc[oo] = fmaf(ap[oo], bs, acc[oo]);
        }
        __syncthreads();
    }
#pragma unroll
    for (int oo = 0; oo < 8; ++oo) {
        int o = og * 8 + oo;
        g_G2[((size_t)o * 4096 + ij0 + ij) * 36 + 32 + s] = 0.5f * acc[oo];
    }
}

// =========================================================================
// kB: one warp per (s,b), grid (4,32), 32 threads (frozen; 26us).
// =========================================================================
__device__ __forceinline__ float2 cmul(float2 a, float2 b) {
    return make_float2(a.x * b.x - a.y * b.y, a.x * b.y + a.y * b.x);
}
__device__ __forceinline__ float2 cadd(float2 a, float2 b) {
    return make_float2(a.x + b.x, a.y + b.y);
}

__global__ __launch_bounds__(32) void kB(const float* __restrict__ qinb,
                                         const float* __restrict__ qw) {
    int s = blockIdx.x;
    int b = blockIdx.y;
    int l = threadIdx.x;

    __shared__ float2 sp[256];

    int q = l & 7, pg = l >> 3;
    float sum = 0.f;
    const float* pp = g_partA + (s * 8 + q) * 32 + b;
#pragma unroll 16
    for (int blk = pg; blk < 512; blk += 4) sum += pp[(size_t)blk * 1024];
    sum += __shfl_xor_sync(0xffffffffu, sum, 8);
    sum += __shfl_xor_sync(0xffffffffu, sum, 16);
    float qv = sum + qinb[s * 8 + q];

    for (int tt = 0; tt < 8; ++tt) {
        int p = l + 32 * tt;
        sp[p] = make_float2(p == 0 ? 1.f : 0.f, 0.f);
    }
    __syncwarp();

    for (int qq = 0; qq < 8; ++qq) {
        float ang = 0.5f * __shfl_sync(0xffffffffu, qv, qq);
        float cg = cosf(ang), sg = sinf(ang);
        int pos = 7 - qq, S = 1 << pos;
#pragma unroll
        for (int tt = 0; tt < 4; ++tt) {
            int p = l + 32 * tt;
            int lo = ((p >> pos) << (pos + 1)) | (p & (S - 1));
            int hi = lo | S;
            float2 v0 = sp[lo], v1 = sp[hi];
            sp[lo] = make_float2(cg * v0.x + sg * v1.y, cg * v0.y - sg * v1.x);
            sp[hi] = make_float2(sg * v0.y + cg * v1.x, -sg * v0.x + cg * v1.y);
        }
        __syncwarp();
    }

    for (int lay = 0; lay < 3; ++lay) {
        for (int qq = 0; qq < 8; ++qq) {
            const float* wp = qw + (((size_t)s * 3 + lay) * 8 + qq) * 3;
            float phi = wp[0], th = wp[1], om = wp[2];
            float ct = cosf(0.5f * th), snt = sinf(0.5f * th);
            float ap = -0.5f * (phi + om), am = -0.5f * (phi - om);
            float2 ep = make_float2(cosf(ap), sinf(ap));
            float2 em = make_float2(cosf(am), sinf(am));
            float2 U00 = make_float2(ep.x * ct, ep.y * ct);
            float2 U01 = make_float2(-em.x * snt, em.y * snt);
            float2 U10 = make_float2(em.x * snt, em.y * snt);
            float2 U11 = make_float2(ep.x * ct, -ep.y * ct);
            int pos = 7 - qq, S = 1 << pos;
#pragma unroll
            for (int tt = 0; tt < 4; ++tt) {
                int p = l + 32 * tt;
                int lo = ((p >> pos) << (pos + 1)) | (p & (S - 1));
                int hi = lo | S;
                float2 v0 = sp[lo], v1 = sp[hi];
                sp[lo] = cadd(cmul(U00, v0), cmul(U01, v1));
                sp[hi] = cadd(cmul(U10, v0), cmul(U11, v1));
            }
            __syncwarp();
        }
        for (int e = 0; e < 8; ++e) {
            int ctrl = (e < 7) ? e : 7;
            int tgt = (e < 7) ? e + 1 : 0;
            int pc = 7 - ctrl, pt = 7 - tgt;
            int plo = pc < pt ? pc : pt;
            int phi_ = pc < pt ? pt : pc;
            int Sc = 1 << pc, St = 1 << pt;
#pragma unroll
            for (int tt = 0; tt < 2; ++tt) {
                int r = l + 32 * tt;
                int tmp = ((r >> plo) << (plo + 1)) | (r & ((1 << plo) - 1));
                int p = ((tmp >> phi_) << (phi_ + 1)) | (tmp & ((1 << phi_) - 1));
                p |= Sc;
                float2 a_ = sp[p], b_ = sp[p | St];
                sp[p] = b_; sp[p | St] = a_;
            }
            __syncwarp();
        }
    }

    float evq[8] = {0, 0, 0, 0, 0, 0, 0, 0};
    for (int tt = 0; tt < 8; ++tt) {
        int p = l + 32 * tt;
        float2 v = sp[p];
        float pr = v.x * v.x + v.y * v.y;
#pragma unroll
        for (int qq = 0; qq < 8; ++qq)
            evq[qq] += ((p >> (7 - qq)) & 1) ? -pr : pr;
    }
#pragma unroll
    for (int qq = 0; qq < 8; ++qq)
        for (int off = 16; off; off >>= 1)
            evq[qq] += __shfl_xor_sync(0xffffffffu, evq[qq], off);
    if (l < 8) g_ev[((size_t)s * 32 + b) * 8 + l] = evq[l];
}

// =========================================================================
// kApply: EXACT R10 version (measured 175.2us). 2 batches per iteration,
// loads issued upfront, G2 row hoisted to registers, stride-40 smem.
// grid (ijt:32, o:128), 256 threads.
// =========================================================================
__global__ __launch_bounds__(256, 3) void kApply(const float* __restrict__ x,
                                                 const float* __restrict__ fuseb,
                                                 float* __restrict__ out) {
    int ijt = blockIdx.x;
    int o = blockIdx.y;
    int ij0 = ijt * 128;
    int t = threadIdx.x;

    __shared__ float G2s[128][40];
    __shared__ float evs[32][36];

    const float* gsrc = g_G2 + ((size_t)o * 4096 + ij0) * 36;
    for (int idx = t; idx < 4608; idx += 256) {
        int ij = idx / 36, k = idx - ij * 36;
        G2s[ij][k] = gsrc[idx];
    }
    for (int idx = t; idx < 1024; idx += 256) {
        int b = idx >> 5, k = idx & 31;
        evs[b][k] = g_ev[((size_t)(k >> 3) * 32 + b) * 8 + (k & 7)];
    }
    __syncthreads();

    int bi = t >> 7, ijl = t & 127;
    int i_ = ijt * 2 + (ijl >> 6), j_ = ijl & 63;
    float fb = fuseb[o];

    float4 g0 = *(const float4*)&G2s[ijl][0];
    float4 g1 = *(const float4*)&G2s[ijl][4];
    float4 g2 = *(const float4*)&G2s[ijl][8];
    float4 g3 = *(const float4*)&G2s[ijl][12];
    float4 g4 = *(const float4*)&G2s[ijl][16];
    float4 g5 = *(const float4*)&G2s[ijl][20];
    float4 g6 = *(const float4*)&G2s[ijl][24];
    float4 g7 = *(const float4*)&G2s[ijl][28];
    float4 g8 = *(const float4*)&G2s[ijl][32];

    size_t rowoff = ((size_t)o * 128 + 2 * i_) * 128 + 2 * j_;

    for (int bo = 0; bo < 8; ++bo) {
        int b0 = bo * 4 + bi * 2;
        int b1 = b0 + 1;
        size_t base0 = (size_t)b0 * 2097152 + rowoff;
        size_t base1 = base0 + 2097152;
        float2 xa0 = *(const float2*)(x + base0);
        float2 xa1 = *(const float2*)(x + base0 + 128);
        float2 xb0 = *(const float2*)(x + base1);
        float2 xb1 = *(const float2*)(x + base1 + 128);

        {
            const float* er = &evs[b0][0];
            float ps0 = g8.x, ps1 = g8.y, ps2 = g8.z, ps3 = g8.w;
            float4 e;
            e = *(const float4*)&er[0];
            ps0 = fmaf(e.x, g0.x, ps0); ps0 = fmaf(e.y, g0.y, ps0);
            ps0 = fmaf(e.z, g0.z, ps0); ps0 = fmaf(e.w, g0.w, ps0);
            e = *(const float4*)&er[4];
            ps0 = fmaf(e.x, g1.x, ps0); ps0 = fmaf(e.y, g1.y, ps0);
            ps0 = fmaf(e.z, g1.z, ps0); ps0 = fmaf(e.w, g1.w, ps0);
            e = *(const float4*)&er[8];
            ps1 = fmaf(e.x, g2.x, ps1); ps1 = fmaf(e.y, g2.y, ps1);
            ps1 = fmaf(e.z, g2.z, ps1); ps1 = fmaf(e.w, g2.w, ps1);
            e = *(const float4*)&er[12];
            ps1 = fmaf(e.x, g3.x, ps1); ps1 = fmaf(e.y, g3.y, ps1);
            ps1 = fmaf(e.z, g3.z, ps1); ps1 = fmaf(e.w, g3.w, ps1);
            e = *(const float4*)&er[16];
            ps2 = fmaf(e.x, g4.x, ps2); ps2 = fmaf(e.y, g4.y, ps2);
            ps2 = fmaf(e.z, g4.z, ps2); ps2 = fmaf(e.w, g4.w, ps2);
            e = *(const float4*)&er[20];
            ps2 = fmaf(e.x, g5.x, ps2); ps2 = fmaf(e.y, g5.y, ps2);
            ps2 = fmaf(e.z, g5.z, ps2); ps2 = fmaf(e.w, g5.w, ps2);
            e = *(const float4*)&er[24];
            ps3 = fmaf(e.x, g6.x, ps3); ps3 = fmaf(e.y, g6.y, ps3);
            ps3 = fmaf(e.z, g6.z, ps3); ps3 = fmaf(e.w, g6.w, ps3);
            e = *(const float4*)&er[28];
            ps3 = fmaf(e.x, g7.x, ps3); ps3 = fmaf(e.y, g7.y, ps3);
            ps3 = fmaf(e.z, g7.z, ps3); ps3 = fmaf(e.w, g7.w, ps3);

            float t00 = ps0 + ps1 + ps2 + ps3;
            float t01 = ps0 + ps1 - ps2 - ps3;
            float t10 = ps0 - ps1 + ps2 - ps3;
            float t11 = ps0 - ps1 - ps2 + ps3;
            *(float2*)(out + base0)       = make_float2(xa0.x + fb + t00, xa0.y + fb + t01);
            *(float2*)(out + base0 + 128) = make_float2(xa1.x + fb + t10, xa1.y + fb + t11);
        }
        {
            const float* er = &evs[b1][0];
            float ps0 = g8.x, ps1 = g8.y, ps2 = g8.z, ps3 = g8.w;
            float4 e;
            e = *(const float4*)&er[0];
            ps0 = fmaf(e.x, g0.x, ps0); ps0 = fmaf(e.y, g0.y, ps0);
            ps0 = fmaf(e.z, g0.z, ps0); ps0 = fmaf(e.w, g0.w, ps0);
            e = *(const float4*)&er[4];
            ps0 = fmaf(e.x, g1.x, ps0); ps0 = fmaf(e.y, g1.y, ps0);
            ps0 = fmaf(e.z, g1.z, ps0); ps0 = fmaf(e.w, g1.w, ps0);
            e = *(const float4*)&er[8];
            ps1 = fmaf(e.x, g2.x, ps1); ps1 = fmaf(e.y, g2.y, ps1);
            ps1 = fmaf(e.z, g2.z, ps1); ps1 = fmaf(e.w, g2.w, ps1);
            e = *(const float4*)&er[12];
            ps1 = fmaf(e.x, g3.x, ps1); ps1 = fmaf(e.y, g3.y, ps1);
            ps1 = fmaf(e.z, g3.z, ps1); ps1 = fmaf(e.w, g3.w, ps1);
            e = *(const float4*)&er[16];
            ps2 = fmaf(e.x, g4.x, ps2); ps2 = fmaf(e.y, g4.y, ps2);
            ps2 = fmaf(e.z, g4.z, ps2); ps2 = fmaf(e.w, g4.w, ps2);
            e = *(const float4*)&er[20];
            ps2 = fmaf(e.x, g5.x, ps2); ps2 = fmaf(e.y, g5.y, ps2);
            ps2 = fmaf(e.z, g5.z, ps2); ps2 = fmaf(e.w, g5.w, ps2);
            e = *(const float4*)&er[24];
            ps3 = fmaf(e.x, g6.x, ps3); ps3 = fmaf(e.y, g6.y, ps3);
            ps3 = fmaf(e.z, g6.z, ps3); ps3 = fmaf(e.w, g6.w, ps3);
            e = *(const float4*)&er[28];
            ps3 = fmaf(e.x, g7.x, ps3); ps3 = fmaf(e.y, g7.y, ps3);
            ps3 = fmaf(e.z, g7.z, ps3); ps3 = fmaf(e.w, g7.w, ps3);

            float t00 = ps0 + ps1 + ps2 + ps3;
            float t01 = ps0 + ps1 - ps2 - ps3;
            float t10 = ps0 - ps1 + ps2 - ps3;
            float t11 = ps0 - ps1 - ps2 + ps3;
            *(float2*)(out + base1)       = make_float2(xb0.x + fb + t00, xb0.y + fb + t01);
            *(float2*)(out + base1 + 128) = make_float2(xb1.x + fb + t10, xb1.y + fb + t11);
        }
    }
}

// =========================================================================
// 5 launches; kGw (the changed kernel) is the 4th -> profiled.
// Deps: kB needs kA; kApply needs kGw + kGb + kB.
// =========================================================================
extern "C" void kernel_launch(void* const* d_in, const int* in_sizes, int n_in,
                              void* d_out, int out_size) {
    const float* x     = (const float*)d_in[0];
    const float* qinW  = (const float*)d_in[1];
    const float* qinb  = (const float*)d_in[2];
    const float* qw    = (const float*)d_in[3];
    const float* qoutW = (const float*)d_in[4];
    const float* qoutb = (const float*)d_in[5];
    const float* fuseW = (const float*)d_in[6];
    const float* fuseb = (const float*)d_in[7];
    float* out = (float*)d_out;

    kA<<<512, 256>>>(x, qinW);
    kGb<<<dim3(256, 4), 256>>>(fuseW, qoutb);
    kB<<<dim3(4, 32), 32>>>(qinb, qw);
    kGw<<<dim3(256, 4), 256>>>(fuseW, qoutW);
    kApply<<<dim3(32, 128), 256>>>(x, fuseb, out);
}

// round 16
// speedup vs baseline: 1.1396x; 1.0430x over previous
#include <cuda_runtime.h>
#include <cuda_bf16.h>

#define FLAT 524288          // 128 * 64 * 64

// ---------------- device scratch (no allocation) ----------------
__device__ float g_partA[512 * 1024];                 // [blk][sq(32)][b(32)]
__device__ float g_ev[4 * 32 * 8];                    // [s][b][q]
__device__ float g_G2[(size_t)128 * 4096 * 36];       // [o][ij][k]  ~75.5 MB

// ---------------- packed f32x2 helpers ----------------
typedef unsigned long long ull;
__device__ __forceinline__ ull pack2(float a, float b) {
    ull r; asm("mov.b64 %0, {%1,%2};" : "=l"(r) : "f"(a), "f"(b)); return r;
}
__device__ __forceinline__ void unpack2(ull v, float& a, float& b) {
    asm("mov.b64 {%0,%1}, %2;" : "=f"(a), "=f"(b) : "l"(v));
}
__device__ __forceinline__ ull ffma2(ull a, ull b, ull c) {
    ull d; asm("fma.rn.f32x2 %0, %1, %2, %3;" : "=l"(d) : "l"(a), "l"(b), "l"(c));
    return d;
}

// =========================================================================
// kA: stage-A partial reductions, register double-buffered (measured 100.2us).
// grid 512 = (c:128) x (igroup:4), 256 threads.
// =========================================================================
__global__ __launch_bounds__(256) void kA(const float* __restrict__ x,
                                          const float* __restrict__ Win) {
    int bx = blockIdx.x;
    int c = bx >> 2;
    int i0 = (bx & 3) << 4;
    int t = threadIdx.x, w = t >> 5, l = t & 31;

    __shared__ float subS[4][64][33];   // [s][j][b]
    __shared__ float Ws[64][36];        // [j][sq]

    float acc0 = 0.f, acc1 = 0.f, acc2 = 0.f, acc3 = 0.f;
    int s_w = w >> 1;

    float wreg[8];
    float4 xr[8];

    {
        const float* wp = Win + (size_t)c * 4096 + (size_t)i0 * 64;
#pragma unroll
        for (int u = 0; u < 8; ++u) {
            int idx = t + 256 * u;
            int sq = idx >> 6, j = idx & 63;
            wreg[u] = wp[(size_t)sq * FLAT + j];
        }
#pragma unroll
        for (int pass = 0; pass < 4; ++pass) {
            int b = w + pass * 8;
            const float* xp = x + ((((size_t)b * 128 + c) * 128) + 2 * i0) * 128;
            xr[2 * pass]     = *(const float4*)(xp + 4 * l);
            xr[2 * pass + 1] = *(const float4*)(xp + 128 + 4 * l);
        }
    }

    for (int ii = 0; ii < 16; ++ii) {
#pragma unroll
        for (int u = 0; u < 8; ++u) {
            int idx = t + 256 * u;
            int sq = idx >> 6, j = idx & 63;
            Ws[j][sq] = wreg[u];
        }
#pragma unroll
        for (int pass = 0; pass < 4; ++pass) {
            int b = w + pass * 8;
            float4 r0 = xr[2 * pass], r1 = xr[2 * pass + 1];
            int j0 = 2 * l;
            float a = r0.x, bb = r0.y, cc = r1.x, dd = r1.y;
            subS[0][j0][b] = 0.5f * (a + bb + cc + dd);
            subS[1][j0][b] = 0.5f * (a + bb - cc - dd);
            subS[2][j0][b] = 0.5f * (a - bb + cc - dd);
            subS[3][j0][b] = 0.5f * (a - bb - cc + dd);
            a = r0.z; bb = r0.w; cc = r1.z; dd = r1.w;
            subS[0][j0 + 1][b] = 0.5f * (a + bb + cc + dd);
            subS[1][j0 + 1][b] = 0.5f * (a + bb - cc - dd);
            subS[2][j0 + 1][b] = 0.5f * (a - bb + cc - dd);
            subS[3][j0 + 1][b] = 0.5f * (a - bb - cc + dd);
        }
        __syncthreads();

        if (ii < 15) {
            int i = i0 + ii + 1;
            const float* wp = Win + (size_t)c * 4096 + (size_t)i * 64;
#pragma unroll
            for (int u = 0; u < 8; ++u) {
                int idx = t + 256 * u;
                int sq = idx >> 6, j = idx & 63;
                wreg[u] = wp[(size_t)sq * FLAT + j];
            }
#pragma unroll
            for (int pass = 0; pass < 4; ++pass) {
                int b = w + pass * 8;
                const float* xp = x + ((((size_t)b * 128 + c) * 128) + 2 * i) * 128;
                xr[2 * pass]     = *(const float4*)(xp + 4 * l);
                xr[2 * pass + 1] = *(const float4*)(xp + 128 + 4 * l);
            }
        }

#pragma unroll 8
        for (int j = 0; j < 64; ++j) {
            float4 wv = *(const float4*)&Ws[j][w * 4];
            float sv = subS[s_w][j][l];
            acc0 = fmaf(sv, wv.x, acc0);
            acc1 = fmaf(sv, wv.y, acc1);
            acc2 = fmaf(sv, wv.z, acc2);
            acc3 = fmaf(sv, wv.w, acc3);
        }
        __syncthreads();
    }
    float* op = g_partA + (size_t)bx * 1024 + (w * 4) * 32 + l;
    op[0] = acc0; op[32] = acc1; op[64] = acc2; op[96] = acc3;
}

// =========================================================================
// kGw: EXACT R5 weights kernel (97.7us by controlled R5->R6 delta).
// grid (ijg:256, s:4, og:2), 256 threads. Block: 64 o x (16 ij x 8 q = 128 n).
// Thread: 8 o x 4 n, acc 16 floats, 64 regs, 3 blocks/SM.
// =========================================================================
__global__ __launch_bounds__(256) void kGw(const float* __restrict__ fuseW,
                                           const float* __restrict__ Wout) {
    __shared__ float As[32][68];    // [cc][o_local]
    __shared__ float Bs[32][128];   // [cc][n]  n = ij*8+q  (coalesced rows)
    int ij0 = blockIdx.x * 16;
    int s = blockIdx.y;
    int o0 = blockIdx.z * 64;
    int t = threadIdx.x;
    int to = t & 31, tn = t >> 5;

    ull acc[8][2];
#pragma unroll
    for (int a = 0; a < 8; ++a) { acc[a][0] = 0ull; acc[a][1] = 0ull; }

    const float* wbase = Wout + (size_t)s * FLAT * 8 + (size_t)ij0 * 8;

    for (int c0 = 0; c0 < 128; c0 += 32) {
        for (int idx = t; idx < 2048; idx += 256) {
            int o = idx >> 5, cc = idx & 31;
            As[cc][o] = fuseW[(o0 + o) * 128 + c0 + cc];
        }
        for (int idx = t; idx < 4096; idx += 256) {
            int cc = idx >> 7, r = idx & 127;
            Bs[cc][r] = wbase[(size_t)(c0 + cc) * 32768 + r];
        }
        __syncthreads();
#pragma unroll 4
        for (int cc = 0; cc < 32; ++cc) {
            ulonglong2 bv = *(const ulonglong2*)&Bs[cc][4 * to];
            float4 av0 = *(const float4*)&As[cc][tn * 8];
            float4 av1 = *(const float4*)&As[cc][tn * 8 + 4];
            ull aa[8];
            aa[0] = pack2(av0.x, av0.x); aa[1] = pack2(av0.y, av0.y);
            aa[2] = pack2(av0.z, av0.z); aa[3] = pack2(av0.w, av0.w);
            aa[4] = pack2(av1.x, av1.x); aa[5] = pack2(av1.y, av1.y);
            aa[6] = pack2(av1.z, av1.z); aa[7] = pack2(av1.w, av1.w);
#pragma unroll
            for (int oo = 0; oo < 8; ++oo) {
                acc[oo][0] = ffma2(aa[oo], bv.x, acc[oo][0]);
                acc[oo][1] = ffma2(aa[oo], bv.y, acc[oo][1]);
            }
        }
        __syncthreads();
    }

    int ij = ij0 + (to >> 1);
    int q = (to & 1) * 4;
#pragma unroll
    for (int oo = 0; oo < 8; ++oo) {
        int o = o0 + tn * 8 + oo;
        float v0, v1, v2, v3;
        unpack2(acc[oo][0], v0, v1);
        unpack2(acc[oo][1], v2, v3);
        *(float4*)&g_G2[((size_t)o * 4096 + ij) * 36 + s * 8 + q] =
            make_float4(0.5f * v0, 0.5f * v1, 0.5f * v2, 0.5f * v3);
    }
}

// =========================================================================
// kGb: EXACT R5 bias kernel (~15us inferred). grid (ijg:128, s:4), 256 thr.
// =========================================================================
__global__ __launch_bounds__(256) void kGb(const float* __restrict__ fuseW,
                                           const float* __restrict__ bout) {
    __shared__ float As[32][132];   // [cc][o]
    __shared__ float Bs[32][33];    // [cc][ij]
    int ij0 = blockIdx.x * 32;
    int s = blockIdx.y;
    int t = threadIdx.x;
    int to = t & 31, tn = t >> 5;

    float acc[16];
#pragma unroll
    for (int a = 0; a < 16; ++a) acc[a] = 0.f;

    const float* bbase = bout + (size_t)s * FLAT + ij0;

    for (int c0 = 0; c0 < 128; c0 += 32) {
        for (int idx = t; idx < 4096; idx += 256) {
            int o = idx >> 5, cc = idx & 31;
            As[cc][o] = fuseW[o * 128 + c0 + cc];
        }
        for (int idx = t; idx < 1024; idx += 256) {
            int cc = idx >> 5, ij = idx & 31;
            Bs[cc][ij] = bbase[(size_t)(c0 + cc) * 4096 + ij];
        }
        __syncthreads();
#pragma unroll 4
        for (int cc = 0; cc < 32; ++cc) {
            float bs = Bs[cc][to];
            const float* ap = &As[cc][tn * 16];
#pragma unroll
            for (int oo = 0; oo < 16; ++oo)
                acc[oo] = fmaf(ap[oo], bs, acc[oo]);
        }
        __syncthreads();
    }

    int ij = ij0 + to;
#pragma unroll
    for (int oo = 0; oo < 16; ++oo) {
        int o = tn * 16 + oo;
        g_G2[((size_t)o * 4096 + ij) * 36 + 32 + s] = 0.5f * acc[oo];
    }
}

// =========================================================================
// kB: one warp per (s,b), grid (4,32), 32 threads (measured 26.0us).
// =========================================================================
__device__ __forceinline__ float2 cmul(float2 a, float2 b) {
    return make_float2(a.x * b.x - a.y * b.y, a.x * b.y + a.y * b.x);
}
__device__ __forceinline__ float2 cadd(float2 a, float2 b) {
    return make_float2(a.x + b.x, a.y + b.y);
}

__global__ __launch_bounds__(32) void kB(const float* __restrict__ qinb,
                                         const float* __restrict__ qw) {
    int s = blockIdx.x;
    int b = blockIdx.y;
    int l = threadIdx.x;

    __shared__ float2 sp[256];

    int q = l & 7, pg = l >> 3;
    float sum = 0.f;
    const float* pp = g_partA + (s * 8 + q) * 32 + b;
#pragma unroll 16
    for (int blk = pg; blk < 512; blk += 4) sum += pp[(size_t)blk * 1024];
    sum += __shfl_xor_sync(0xffffffffu, sum, 8);
    sum += __shfl_xor_sync(0xffffffffu, sum, 16);
    float qv = sum + qinb[s * 8 + q];

    for (int tt = 0; tt < 8; ++tt) {
        int p = l + 32 * tt;
        sp[p] = make_float2(p == 0 ? 1.f : 0.f, 0.f);
    }
    __syncwarp();

    for (int qq = 0; qq < 8; ++qq) {
        float ang = 0.5f * __shfl_sync(0xffffffffu, qv, qq);
        float cg = cosf(ang), sg = sinf(ang);
        int pos = 7 - qq, S = 1 << pos;
#pragma unroll
        for (int tt = 0; tt < 4; ++tt) {
            int p = l + 32 * tt;
            int lo = ((p >> pos) << (pos + 1)) | (p & (S - 1));
            int hi = lo | S;
            float2 v0 = sp[lo], v1 = sp[hi];
            sp[lo] = make_float2(cg * v0.x + sg * v1.y, cg * v0.y - sg * v1.x);
            sp[hi] = make_float2(sg * v0.y + cg * v1.x, -sg * v0.x + cg * v1.y);
        }
        __syncwarp();
    }

    for (int lay = 0; lay < 3; ++lay) {
        for (int qq = 0; qq < 8; ++qq) {
            const float* wp = qw + (((size_t)s * 3 + lay) * 8 + qq) * 3;
            float phi = wp[0], th = wp[1], om = wp[2];
            float ct = cosf(0.5f * th), snt = sinf(0.5f * th);
            float ap = -0.5f * (phi + om), am = -0.5f * (phi - om);
            float2 ep = make_float2(cosf(ap), sinf(ap));
            float2 em = make_float2(cosf(am), sinf(am));
            float2 U00 = make_float2(ep.x * ct, ep.y * ct);
            float2 U01 = make_float2(-em.x * snt, em.y * snt);
            float2 U10 = make_float2(em.x * snt, em.y * snt);
            float2 U11 = make_float2(ep.x * ct, -ep.y * ct);
            int pos = 7 - qq, S = 1 << pos;
#pragma unroll
            for (int tt = 0; tt < 4; ++tt) {
                int p = l + 32 * tt;
                int lo = ((p >> pos) << (pos + 1)) | (p & (S - 1));
                int hi = lo | S;
                float2 v0 = sp[lo], v1 = sp[hi];
                sp[lo] = cadd(cmul(U00, v0), cmul(U01, v1));
                sp[hi] = cadd(cmul(U10, v0), cmul(U11, v1));
            }
            __syncwarp();
        }
        for (int e = 0; e < 8; ++e) {
            int ctrl = (e < 7) ? e : 7;
            int tgt = (e < 7) ? e + 1 : 0;
            int pc = 7 - ctrl, pt = 7 - tgt;
            int plo = pc < pt ? pc : pt;
            int phi_ = pc < pt ? pt : pc;
            int Sc = 1 << pc, St = 1 << pt;
#pragma unroll
            for (int tt = 0; tt < 2; ++tt) {
                int r = l + 32 * tt;
                int tmp = ((r >> plo) << (plo + 1)) | (r & ((1 << plo) - 1));
                int p = ((tmp >> phi_) << (phi_ + 1)) | (tmp & ((1 << phi_) - 1));
                p |= Sc;
                float2 a_ = sp[p], b_ = sp[p | St];
                sp[p] = b_; sp[p | St] = a_;
            }
            __syncwarp();
        }
    }

    float evq[8] = {0, 0, 0, 0, 0, 0, 0, 0};
    for (int tt = 0; tt < 8; ++tt) {
        int p = l + 32 * tt;
        float2 v = sp[p];
        float pr = v.x * v.x + v.y * v.y;
#pragma unroll
        for (int qq = 0; qq < 8; ++qq)
            evq[qq] += ((p >> (7 - qq)) & 1) ? -pr : pr;
    }
#pragma unroll
    for (int qq = 0; qq < 8; ++qq)
        for (int off = 16; off; off >>= 1)
            evq[qq] += __shfl_xor_sync(0xffffffffu, evq[qq], off);
    if (l < 8) g_ev[((size_t)s * 32 + b) * 8 + l] = evq[l];
}

// =========================================================================
// kApply: EXACT R10 version (measured 175.2us).
// grid (ijt:32, o:128), 256 threads.
// =========================================================================
__global__ __launch_bounds__(256, 3) void kApply(const float* __restrict__ x,
                                                 const float* __restrict__ fuseb,
                                                 float* __restrict__ out) {
    int ijt = blockIdx.x;
    int o = blockIdx.y;
    int ij0 = ijt * 128;
    int t = threadIdx.x;

    __shared__ float G2s[128][40];
    __shared__ float evs[32][36];

    const float* gsrc = g_G2 + ((size_t)o * 4096 + ij0) * 36;
    for (int idx = t; idx < 4608; idx += 256) {
        int ij = idx / 36, k = idx - ij * 36;
        G2s[ij][k] = gsrc[idx];
    }
    for (int idx = t; idx < 1024; idx += 256) {
        int b = idx >> 5, k = idx & 31;
        evs[b][k] = g_ev[((size_t)(k >> 3) * 32 + b) * 8 + (k & 7)];
    }
    __syncthreads();

    int bi = t >> 7, ijl = t & 127;
    int i_ = ijt * 2 + (ijl >> 6), j_ = ijl & 63;
    float fb = fuseb[o];

    float4 g0 = *(const float4*)&G2s[ijl][0];
    float4 g1 = *(const float4*)&G2s[ijl][4];
    float4 g2 = *(const float4*)&G2s[ijl][8];
    float4 g3 = *(const float4*)&G2s[ijl][12];
    float4 g4 = *(const float4*)&G2s[ijl][16];
    float4 g5 = *(const float4*)&G2s[ijl][20];
    float4 g6 = *(const float4*)&G2s[ijl][24];
    float4 g7 = *(const float4*)&G2s[ijl][28];
    float4 g8 = *(const float4*)&G2s[ijl][32];

    size_t rowoff = ((size_t)o * 128 + 2 * i_) * 128 + 2 * j_;

    for (int bo = 0; bo < 8; ++bo) {
        int b0 = bo * 4 + bi * 2;
        int b1 = b0 + 1;
        size_t base0 = (size_t)b0 * 2097152 + rowoff;
        size_t base1 = base0 + 2097152;
        float2 xa0 = *(const float2*)(x + base0);
        float2 xa1 = *(const float2*)(x + base0 + 128);
        float2 xb0 = *(const float2*)(x + base1);
        float2 xb1 = *(const float2*)(x + base1 + 128);

        {
            const float* er = &evs[b0][0];
            float ps0 = g8.x, ps1 = g8.y, ps2 = g8.z, ps3 = g8.w;
            float4 e;
            e = *(const float4*)&er[0];
            ps0 = fmaf(e.x, g0.x, ps0); ps0 = fmaf(e.y, g0.y, ps0);
            ps0 = fmaf(e.z, g0.z, ps0); ps0 = fmaf(e.w, g0.w, ps0);
            e = *(const float4*)&er[4];
            ps0 = fmaf(e.x, g1.x, ps0); ps0 = fmaf(e.y, g1.y, ps0);
            ps0 = fmaf(e.z, g1.z, ps0); ps0 = fmaf(e.w, g1.w, ps0);
            e = *(const float4*)&er[8];
            ps1 = fmaf(e.x, g2.x, ps1); ps1 = fmaf(e.y, g2.y, ps1);
            ps1 = fmaf(e.z, g2.z, ps1); ps1 = fmaf(e.w, g2.w, ps1);
            e = *(const float4*)&er[12];
            ps1 = fmaf(e.x, g3.x, ps1); ps1 = fmaf(e.y, g3.y, ps1);
            ps1 = fmaf(e.z, g3.z, ps1); ps1 = fmaf(e.w, g3.w, ps1);
            e = *(const float4*)&er[16];
            ps2 = fmaf(e.x, g4.x, ps2); ps2 = fmaf(e.y, g4.y, ps2);
            ps2 = fmaf(e.z, g4.z, ps2); ps2 = fmaf(e.w, g4.w, ps2);
            e = *(const float4*)&er[20];
            ps2 = fmaf(e.x, g5.x, ps2); ps2 = fmaf(e.y, g5.y, ps2);
            ps2 = fmaf(e.z, g5.z, ps2); ps2 = fmaf(e.w, g5.w, ps2);
            e = *(const float4*)&er[24];
            ps3 = fmaf(e.x, g6.x, ps3); ps3 = fmaf(e.y, g6.y, ps3);
            ps3 = fmaf(e.z, g6.z, ps3); ps3 = fmaf(e.w, g6.w, ps3);
            e = *(const float4*)&er[28];
            ps3 = fmaf(e.x, g7.x, ps3); ps3 = fmaf(e.y, g7.y, ps3);
            ps3 = fmaf(e.z, g7.z, ps3); ps3 = fmaf(e.w, g7.w, ps3);

            float t00 = ps0 + ps1 + ps2 + ps3;
            float t01 = ps0 + ps1 - ps2 - ps3;
            float t10 = ps0 - ps1 + ps2 - ps3;
            float t11 = ps0 - ps1 - ps2 + ps3;
            *(float2*)(out + base0)       = make_float2(xa0.x + fb + t00, xa0.y + fb + t01);
            *(float2*)(out + base0 + 128) = make_float2(xa1.x + fb + t10, xa1.y + fb + t11);
        }
        {
            const float* er = &evs[b1][0];
            float ps0 = g8.x, ps1 = g8.y, ps2 = g8.z, ps3 = g8.w;
            float4 e;
            e = *(const float4*)&er[0];
            ps0 = fmaf(e.x, g0.x, ps0); ps0 = fmaf(e.y, g0.y, ps0);
            ps0 = fmaf(e.z, g0.z, ps0); ps0 = fmaf(e.w, g0.w, ps0);
            e = *(const float4*)&er[4];
            ps0 = fmaf(e.x, g1.x, ps0); ps0 = fmaf(e.y, g1.y, ps0);
            ps0 = fmaf(e.z, g1.z, ps0); ps0 = fmaf(e.w, g1.w, ps0);
            e = *(const float4*)&er[8];
            ps1 = fmaf(e.x, g2.x, ps1); ps1 = fmaf(e.y, g2.y, ps1);
            ps1 = fmaf(e.z, g2.z, ps1); ps1 = fmaf(e.w, g2.w, ps1);
            e = *(const float4*)&er[12];
            ps1 = fmaf(e.x, g3.x, ps1); ps1 = fmaf(e.y, g3.y, ps1);
            ps1 = fmaf(e.z, g3.z, ps1); ps1 = fmaf(e.w, g3.w, ps1);
            e = *(const float4*)&er[16];
            ps2 = fmaf(e.x, g4.x, ps2); ps2 = fmaf(e.y, g4.y, ps2);
            ps2 = fmaf(e.z, g4.z, ps2); ps2 = fmaf(e.w, g4.w, ps2);
            e = *(const float4*)&er[20];
            ps2 = fmaf(e.x, g5.x, ps2); ps2 = fmaf(e.y, g5.y, ps2);
            ps2 = fmaf(e.z, g5.z, ps2); ps2 = fmaf(e.w, g5.w, ps2);
            e = *(const float4*)&er[24];
            ps3 = fmaf(e.x, g6.x, ps3); ps3 = fmaf(e.y, g6.y, ps3);
            ps3 = fmaf(e.z, g6.z, ps3); ps3 = fmaf(e.w, g6.w, ps3);
            e = *(const float4*)&er[28];
            ps3 = fmaf(e.x, g7.x, ps3); ps3 = fmaf(e.y, g7.y, ps3);
            ps3 = fmaf(e.z, g7.z, ps3); ps3 = fmaf(e.w, g7.w, ps3);

            float t00 = ps0 + ps1 + ps2 + ps3;
            float t01 = ps0 + ps1 - ps2 - ps3;
            float t10 = ps0 - ps1 + ps2 - ps3;
            float t11 = ps0 - ps1 - ps2 + ps3;
            *(float2*)(out + base1)       = make_float2(xb0.x + fb + t00, xb0.y + fb + t01);
            *(float2*)(out + base1 + 128) = make_float2(xb1.x + fb + t10, xb1.y + fb + t11);
        }
    }
}

// =========================================================================
// 5 launches; kGw (the reverted, 97.7us-expected kernel) is 4th -> profiled.
// Deps: kB needs kA; kApply needs kGw + kGb + kB.
// =========================================================================
extern "C" void kernel_launch(void* const* d_in, const int* in_sizes, int n_in,
                              void* d_out, int out_size) {
    const float* x     = (const float*)d_in[0];
    const float* qinW  = (const float*)d_in[1];
    const float* qinb  = (const float*)d_in[2];
    const float* qw    = (const float*)d_in[3];
    const float* qoutW = (const float*)d_in[4];
    const float* qoutb = (const float*)d_in[5];
    const float* fuseW = (const float*)d_in[6];
    const float* fuseb = (const float*)d_in[7];
    float* out = (float*)d_out;

    kA<<<512, 256>>>(x, qinW);
    kGb<<<dim3(128, 4), 256>>>(fuseW, qoutb);
    kB<<<dim3(4, 32), 32>>>(qinb, qw);
    kGw<<<dim3(256, 4, 2), 256>>>(fuseW, qoutW);
    kApply<<<dim3(32, 128), 256>>>(x, fuseb, out);
}